// round 1
// baseline (speedup 1.0000x reference)
#include <cuda_runtime.h>

// Problem constants (fixed by setup_inputs)
#define BHALF  4096
#define NTOT   8192
#define DIMS   256
#define NSPLIT 8
#define NGROUP 4

// Scratch (device globals; no allocations allowed)
__device__ float g_zn[(size_t)NTOT * DIMS];        // normalized rows, 8 MB
__device__ float g_den[(size_t)NTOT * NSPLIT];     // per-row den partials per col-split
__device__ float g_pos[BHALF];                      // pos diagonal dots
__device__ float g_vpart[NGROUP * 32 * DIMS];      // per-(group,chunk) vector sums

// ---------------------------------------------------------------------------
// 1) Row normalize: zn = z / max(||z||, eps)
// ---------------------------------------------------------------------------
__global__ void norm_kernel(const float* __restrict__ zi, const float* __restrict__ zj) {
    int row = blockIdx.x;
    int t   = threadIdx.x;
    const float* src = (row < BHALF) ? (zi + (size_t)row * DIMS)
                                     : (zj + (size_t)(row - BHALF) * DIMS);
    float v = src[t];
    __shared__ float red[DIMS];
    red[t] = v * v;
    __syncthreads();
    for (int s = DIMS / 2; s > 0; s >>= 1) {
        if (t < s) red[t] += red[t + s];
        __syncthreads();
    }
    float norm = fmaxf(sqrtf(red[0]), 1e-8f);
    g_zn[(size_t)row * DIMS + t] = v / norm;
}

// ---------------------------------------------------------------------------
// 2) pos_k = zn[k] . zn[k+B]
// ---------------------------------------------------------------------------
__global__ void pos_kernel() {
    int k = blockIdx.x;
    int t = threadIdx.x;
    float p = g_zn[(size_t)k * DIMS + t] * g_zn[(size_t)(k + BHALF) * DIMS + t];
    __shared__ float red[DIMS];
    red[t] = p;
    __syncthreads();
    for (int s = DIMS / 2; s > 0; s >>= 1) {
        if (t < s) red[t] += red[t + s];
        __syncthreads();
    }
    if (t == 0) g_pos[k] = red[0];
}

// ---------------------------------------------------------------------------
// 3) den pass: for each row i, sum_{j != i} exp(2 * zn_i . zn_j)
//    128x128 output tile per block iteration, 8x8 per-thread microtile, TK=8.
//    grid = (64 row tiles, 8 column splits); each block walks 8 col tiles.
// ---------------------------------------------------------------------------
__global__ __launch_bounds__(256, 2) void den_kernel() {
    __shared__ float As[8][132];       // k-major, padded: stores conflict-free,
    __shared__ float Bs[8][132];       // rows 16B-aligned for float4 loads
    __shared__ float red[128][17];     // per-row partial reduction buffer

    const int rt      = blockIdx.x;
    const int sp      = blockIdx.y;
    const int rowBase = rt * 128;
    const int tid     = threadIdx.x;
    const int tx      = tid & 15;      // 16 col-thread groups
    const int ty      = tid >> 4;      // 16 row-thread groups
    const int lrow    = tid >> 1;      // loader: row 0..127
    const int kq      = (tid & 1) * 4; // loader: k quad 0 or 4

    float dacc = 0.f;                  // valid for tid < 128 (row rowBase+tid)

    for (int ct = 0; ct < 8; ct++) {
        const int colBase = sp * 1024 + ct * 128;

        float acc[8][8];
#pragma unroll
        for (int i = 0; i < 8; i++)
#pragma unroll
            for (int j = 0; j < 8; j++) acc[i][j] = 0.f;

        for (int kk = 0; kk < DIMS; kk += 8) {
            __syncthreads();
            float4 a4 = *(const float4*)&g_zn[(size_t)(rowBase + lrow) * DIMS + kk + kq];
            float4 b4 = *(const float4*)&g_zn[(size_t)(colBase + lrow) * DIMS + kk + kq];
            As[kq + 0][lrow] = a4.x; As[kq + 1][lrow] = a4.y;
            As[kq + 2][lrow] = a4.z; As[kq + 3][lrow] = a4.w;
            Bs[kq + 0][lrow] = b4.x; Bs[kq + 1][lrow] = b4.y;
            Bs[kq + 2][lrow] = b4.z; Bs[kq + 3][lrow] = b4.w;
            __syncthreads();
#pragma unroll
            for (int k = 0; k < 8; k++) {
                float4 a0 = *(const float4*)&As[k][ty * 8];
                float4 a1 = *(const float4*)&As[k][ty * 8 + 4];
                float4 b0 = *(const float4*)&Bs[k][tx * 8];
                float4 b1 = *(const float4*)&Bs[k][tx * 8 + 4];
                float av[8] = {a0.x, a0.y, a0.z, a0.w, a1.x, a1.y, a1.z, a1.w};
                float bv[8] = {b0.x, b0.y, b0.z, b0.w, b1.x, b1.y, b1.z, b1.w};
#pragma unroll
                for (int i = 0; i < 8; i++)
#pragma unroll
                    for (int j = 0; j < 8; j++)
                        acc[i][j] = fmaf(av[i], bv[j], acc[i][j]);
            }
        }

        // exp(S/T) with T = 0.5, skip diagonal (i == j), per-thread row sums
        const int grb = rowBase + ty * 8;
        const int gcb = colBase + tx * 8;
        float rsum[8];
#pragma unroll
        for (int i = 0; i < 8; i++) {
            float rs = 0.f;
#pragma unroll
            for (int j = 0; j < 8; j++) {
                float e = __expf(2.0f * acc[i][j]);
                rs += ((grb + i) == (gcb + j)) ? 0.f : e;
            }
            rsum[i] = rs;
        }
        __syncthreads();
#pragma unroll
        for (int i = 0; i < 8; i++) red[ty * 8 + i][tx] = rsum[i];
        __syncthreads();
        if (tid < 128) {
            float s = 0.f;
#pragma unroll
            for (int x = 0; x < 16; x++) s += red[tid][x];   // fixed order
            dacc += s;
        }
    }
    if (tid < 128) g_den[(size_t)(rowBase + tid) * NSPLIT + sp] = dacc;
}

// ---------------------------------------------------------------------------
// 4) Per-(group, row-chunk) vector sums of zn[:B]
// ---------------------------------------------------------------------------
__global__ void group_kernel(const long long* __restrict__ sf) {
    int g     = blockIdx.x;
    int chunk = blockIdx.y;
    int t     = threadIdx.x;
    int base  = chunk * 128;
    float acc = 0.f;
    for (int r = 0; r < 128; r++) {
        long long s = sf[base + r];
        if ((int)s == g) acc += g_zn[(size_t)(base + r) * DIMS + t];
    }
    g_vpart[(g * 32 + chunk) * DIMS + t] = acc;
}

// ---------------------------------------------------------------------------
// 5) Final deterministic reductions + scalar assembly
// ---------------------------------------------------------------------------
__global__ void final_kernel(const long long* __restrict__ sf, float* __restrict__ out) {
    int t = threadIdx.x;
    __shared__ float red[256];
    __shared__ int   redi[256];
    __shared__ float gsum[NGROUP];
    __shared__ int   counts[NGROUP];

    // group counts (exact ints)
    int carr[NGROUP] = {0, 0, 0, 0};
    for (int r = t; r < BHALF; r += 256) {
        int g = (int)sf[r];
        carr[0] += (g == 0); carr[1] += (g == 1);
        carr[2] += (g == 2); carr[3] += (g == 3);
    }
    for (int g = 0; g < NGROUP; g++) {
        redi[t] = carr[g];
        __syncthreads();
        for (int s = 128; s > 0; s >>= 1) {
            if (t < s) redi[t] += redi[t + s];
            __syncthreads();
        }
        if (t == 0) counts[g] = redi[0];
        __syncthreads();
    }

    // group_sums[g] = || sum_{i in g} zn_i ||^2
    for (int g = 0; g < NGROUP; g++) {
        float v = 0.f;
        for (int ch = 0; ch < 32; ch++) v += g_vpart[(g * 32 + ch) * DIMS + t];
        red[t] = v * v;
        __syncthreads();
        for (int s = 128; s > 0; s >>= 1) {
            if (t < s) red[t] += red[t + s];
            __syncthreads();
        }
        if (t == 0) gsum[g] = red[0];
        __syncthreads();
    }

    // sum over rows of log(den_i)
    float l = 0.f;
    for (int r = t; r < NTOT; r += 256) {
        float d = 0.f;
#pragma unroll
        for (int s2 = 0; s2 < NSPLIT; s2++) d += g_den[(size_t)r * NSPLIT + s2];
        l += logf(d);
    }
    red[t] = l;
    __syncthreads();
    for (int s = 128; s > 0; s >>= 1) {
        if (t < s) red[t] += red[t + s];
        __syncthreads();
    }
    float sumlog = red[0];
    __syncthreads();

    // sum of pos (half diagonal; appears twice in reference)
    float p = 0.f;
    for (int k = t; k < BHALF; k += 256) p += g_pos[k];
    red[t] = p;
    __syncthreads();
    for (int s = 128; s > 0; s >>= 1) {
        if (t < s) red[t] += red[t + s];
        __syncthreads();
    }

    if (t == 0) {
        float possum = red[0];
        // sum(-pos/T) over 2B entries = -(1/T) * 2 * possum = -4 * possum  (T=0.5)
        float contrastive = (sumlog - 4.0f * possum) / (float)NTOT;

        float fair_acc = 0.f, nuniq = 0.f;
        for (int g = 0; g < NGROUP; g++) {
            float c = (float)counts[g];
            if (c > 0.f) nuniq += 1.f;
            if (c > 1.f) fair_acc += gsum[g] / (c * (c - 1.f));
        }
        float fairness = 0.1f * (fair_acc / fmaxf(nuniq, 1.f));
        out[0] = contrastive + fairness;
    }
}

// ---------------------------------------------------------------------------
extern "C" void kernel_launch(void* const* d_in, const int* in_sizes, int n_in,
                              void* d_out, int out_size) {
    const float*     zi  = (const float*)d_in[0];
    const float*     zj  = (const float*)d_in[1];
    const long long* sf  = (const long long*)d_in[2];
    float*           out = (float*)d_out;

    norm_kernel<<<NTOT, DIMS>>>(zi, zj);
    pos_kernel<<<BHALF, DIMS>>>();
    den_kernel<<<dim3(64, NSPLIT), 256>>>();
    group_kernel<<<dim3(NGROUP, 32), 256>>>(sf);
    final_kernel<<<1, 256>>>(sf, out);
}

// round 3
// speedup vs baseline: 5.3464x; 5.3464x over previous
#include <cuda_runtime.h>

// Problem constants (fixed by setup_inputs)
#define BHALF  4096
#define NTOT   8192
#define DIMS   256
#define NPART  16          // den partials per row: 8 col-splits x 2 warp col-groups
#define NGROUP 4
#define GCHUNK 64

// ---------------------------------------------------------------------------
// Scratch (device globals; no allocations allowed)
// ---------------------------------------------------------------------------
__device__ float g_zn[(size_t)NTOT * DIMS];                              // normalized fp32 (8 MB)
__device__ __align__(1024) unsigned char g_znh[(size_t)NTOT * DIMS * 2]; // bf16, SW128-swizzled per 128-row tile (4 MB)
__device__ float g_den[(size_t)NTOT * NPART];
__device__ float g_pos[BHALF];
__device__ float g_vpart[NGROUP * GCHUNK * DIMS];

// ---------------------------------------------------------------------------
// PTX helpers (family-portable only: cp.async, ldmatrix, mma.sync)
// ---------------------------------------------------------------------------
__device__ __forceinline__ unsigned smem_u32(const void* p) {
    unsigned a;
    asm("{ .reg .u64 t; cvta.to.shared.u64 t, %1; cvt.u32.u64 %0, t; }" : "=r"(a) : "l"(p));
    return a;
}
__device__ __forceinline__ void cp16(unsigned dst, const void* src) {
    asm volatile("cp.async.cg.shared.global [%0], [%1], 16;" :: "r"(dst), "l"(src) : "memory");
}
#define CP_COMMIT() asm volatile("cp.async.commit_group;" ::: "memory")
#define CP_WAIT(n)  asm volatile("cp.async.wait_group %0;" :: "n"(n) : "memory")

#define LDSM4(r0, r1, r2, r3, a)                                              \
    asm volatile("ldmatrix.sync.aligned.m8n8.x4.shared.b16 {%0,%1,%2,%3}, [%4];" \
                 : "=r"(r0), "=r"(r1), "=r"(r2), "=r"(r3) : "r"(a))

#define MMA16816(d, a, b0, b1)                                                \
    asm volatile("mma.sync.aligned.m16n8k16.row.col.f32.bf16.bf16.f32 "       \
                 "{%0,%1,%2,%3}, {%4,%5,%6,%7}, {%8,%9}, {%0,%1,%2,%3};"      \
                 : "+f"((d)[0]), "+f"((d)[1]), "+f"((d)[2]), "+f"((d)[3])     \
                 : "r"((a)[0]), "r"((a)[1]), "r"((a)[2]), "r"((a)[3]),        \
                   "r"(b0), "r"(b1))

// exp(2*S) = exp2(S * 2/ln2), deg-5 minimax-ish Taylor on [-0.5,0.5], rel err < 3e-6
__device__ __forceinline__ float fexp2s(float s) {
    float x  = s * 2.885390081777927f;
    float fx = x + 12582912.0f;
    int   ix = __float_as_int(fx);
    float fl = fx - 12582912.0f;
    float f  = x - fl;
    float p  = 1.3333558146428443e-3f;
    p = fmaf(p, f, 9.6181291076284772e-3f);
    p = fmaf(p, f, 5.5504108664798463e-2f);
    p = fmaf(p, f, 2.4022650695910072e-1f);
    p = fmaf(p, f, 6.9314718055994531e-1f);
    p = fmaf(p, f, 1.0f);
    return __int_as_float(__float_as_int(p) + (ix << 23));
}

// ---------------------------------------------------------------------------
// 1) Normalize; emit fp32 rows (g_zn) + bf16 rows pre-swizzled per 128-row
//    tile: atom = 8 rows x 128B (SW128), atoms tiled (16 atom-rows, 4
//    atom-cols), tile stride 64KB. XOR mask is (row&7)<<4.
// ---------------------------------------------------------------------------
__global__ void norm_kernel(const float* __restrict__ zi, const float* __restrict__ zj) {
    int row = blockIdx.x;
    int t   = threadIdx.x;   // 0..127 -> cols 2t, 2t+1
    const float* src = (row < BHALF) ? (zi + (size_t)row * DIMS)
                                     : (zj + (size_t)(row - BHALF) * DIMS);
    float2 v = ((const float2*)src)[t];
    __shared__ float red[128];
    red[t] = v.x * v.x + v.y * v.y;
    __syncthreads();
    for (int s = 64; s > 0; s >>= 1) {
        if (t < s) red[t] += red[t + s];
        __syncthreads();
    }
    float norm = fmaxf(sqrtf(red[0]), 1e-8f);
    float nx = v.x / norm, ny = v.y / norm;
    ((float2*)&g_zn[(size_t)row * DIMS])[t] = make_float2(nx, ny);

    unsigned pk;
    asm("cvt.rn.bf16x2.f32 %0, %1, %2;" : "=r"(pk) : "f"(ny), "f"(nx)); // hi=ny, lo=nx
    int tile = row >> 7, irow = row & 127, col = 2 * t;
    unsigned off = (unsigned)((irow >> 3) + (col >> 6) * 16) * 1024u
                 + (unsigned)(irow & 7) * 128u + (unsigned)(col & 63) * 2u;
    unsigned sw = off ^ ((off >> 3) & 0x70);
    *(unsigned*)(g_znh + (size_t)tile * 65536 + sw) = pk;
}

// ---------------------------------------------------------------------------
// 2) pos_k = zn[k] . zn[k+B]  (fp32)
// ---------------------------------------------------------------------------
__global__ void pos_kernel() {
    int k = blockIdx.x;
    int t = threadIdx.x;   // 0..127
    float2 a = ((const float2*)&g_zn[(size_t)k * DIMS])[t];
    float2 b = ((const float2*)&g_zn[(size_t)(k + BHALF) * DIMS])[t];
    __shared__ float red[128];
    red[t] = a.x * b.x + a.y * b.y;
    __syncthreads();
    for (int s = 64; s > 0; s >>= 1) {
        if (t < s) red[t] += red[t + s];
        __syncthreads();
    }
    if (t == 0) g_pos[k] = red[0];
}

// ---------------------------------------------------------------------------
// 3) den pass with mma.sync bf16 (HMMA). Grid (64 row tiles, 8 col splits);
//    each CTA loads its A tile once and walks 8 B tiles (double-buffered).
//    8 warps: warp tile 32 rows x 64 cols; m16n8k16 fragments via ldmatrix.
// ---------------------------------------------------------------------------
#define SMB0 65536
#define SMB1 131072
#define SM_TOTAL 196608

__global__ __launch_bounds__(256, 1) void den_mma_kernel() {
    extern __shared__ __align__(1024) unsigned char smem[];
    const unsigned sb = smem_u32(smem);
    const int tid = threadIdx.x, wid = tid >> 5, lane = tid & 31;
    const int g = lane >> 2, tig = lane & 3;
    const int warpR = (wid >> 1) * 32;
    const int warpC = (wid & 1) * 64;
    const int rowBase = blockIdx.x * 128;
    const int sp = blockIdx.y;

    // Issue A + B0 (group 0), B1 (group 1): verbatim 64KB tile copies
    {
        const unsigned char* As = g_znh + (size_t)blockIdx.x * 65536;
        const unsigned char* B0 = g_znh + (size_t)(sp * 8 + 0) * 65536;
#pragma unroll
        for (int i = 0; i < 16; i++) {
            unsigned o = i * 4096 + tid * 16;
            cp16(sb + o, As + o);
            cp16(sb + SMB0 + o, B0 + o);
        }
        CP_COMMIT();
        const unsigned char* B1 = g_znh + (size_t)(sp * 8 + 1) * 65536;
#pragma unroll
        for (int i = 0; i < 16; i++) {
            unsigned o = i * 4096 + tid * 16;
            cp16(sb + SMB1 + o, B1 + o);
        }
        CP_COMMIT();
    }

    // Per-lane ldmatrix base offsets (tile-relative, un-XORed)
    const int m   = lane >> 3;
    const int rin = lane & 7;
    const unsigned xr = (unsigned)rin << 4;
    unsigned aOff[2], bOff[4];
#pragma unroll
    for (int mt = 0; mt < 2; mt++) {
        int arow = warpR + mt * 16 + (m & 1) * 8 + rin;
        aOff[mt] = (unsigned)(arow >> 3) * 1024u + (unsigned)rin * 128u + (unsigned)(m >> 1) * 16u;
    }
#pragma unroll
    for (int grp = 0; grp < 4; grp++) {
        int nrow = warpC + (2 * grp + (m >> 1)) * 8 + rin;
        bOff[grp] = (unsigned)(nrow >> 3) * 1024u + (unsigned)rin * 128u + (unsigned)(m & 1) * 16u;
    }

    float rs[2][2] = {{0.f, 0.f}, {0.f, 0.f}};

    for (int ct = 0; ct < 8; ct++) {
        CP_WAIT(1);
        __syncthreads();
        const unsigned sB = sb + ((ct & 1) ? SMB1 : SMB0);

        float acc[2][8][4];
#pragma unroll
        for (int mt = 0; mt < 2; mt++)
#pragma unroll
            for (int nt = 0; nt < 8; nt++)
#pragma unroll
                for (int q = 0; q < 4; q++) acc[mt][nt][q] = 0.f;

#pragma unroll 4
        for (int ks = 0; ks < 16; ks++) {
            const unsigned d = (unsigned)(ks >> 2) * 16384u + (unsigned)(ks & 3) * 32u;
            unsigned a[2][4];
            LDSM4(a[0][0], a[0][1], a[0][2], a[0][3], sb + ((aOff[0] + d) ^ xr));
            LDSM4(a[1][0], a[1][1], a[1][2], a[1][3], sb + ((aOff[1] + d) ^ xr));
            unsigned b[4][4];
#pragma unroll
            for (int grp = 0; grp < 4; grp++)
                LDSM4(b[grp][0], b[grp][1], b[grp][2], b[grp][3], sB + ((bOff[grp] + d) ^ xr));
#pragma unroll
            for (int mt = 0; mt < 2; mt++)
#pragma unroll
                for (int nt = 0; nt < 8; nt++)
                    MMA16816(acc[mt][nt], a[mt], b[nt >> 1][(nt & 1) * 2], b[nt >> 1][(nt & 1) * 2 + 1]);
        }

        __syncthreads();                 // everyone done reading B[ct&1]
        if (ct + 2 < 8) {
            const unsigned char* Bn = g_znh + (size_t)(sp * 8 + ct + 2) * 65536;
            unsigned sBn = sb + ((ct & 1) ? SMB1 : SMB0);
#pragma unroll
            for (int i = 0; i < 16; i++) {
                unsigned o = i * 4096 + tid * 16;
                cp16(sBn + o, Bn + o);
            }
        }
        CP_COMMIT();                     // commit (possibly empty group)

        // Epilogue: exp + row-sum accumulation (runs while prefetch is in flight)
        const bool hasDiag = ((int)blockIdx.x == sp * 8 + ct);
#pragma unroll
        for (int mt = 0; mt < 2; mt++) {
#pragma unroll
            for (int nt = 0; nt < 8; nt++) {
                float e0 = fexp2s(acc[mt][nt][0]);
                float e1 = fexp2s(acc[mt][nt][1]);
                float e2 = fexp2s(acc[mt][nt][2]);
                float e3 = fexp2s(acc[mt][nt][3]);
                if (hasDiag) {
                    int r0 = warpR + mt * 16 + g;
                    int cc = warpC + nt * 8 + tig * 2;
                    if (r0 == cc)     e0 = 0.f;
                    if (r0 == cc + 1) e1 = 0.f;
                    if (r0 + 8 == cc)     e2 = 0.f;
                    if (r0 + 8 == cc + 1) e3 = 0.f;
                }
                rs[mt][0] += e0 + e1;
                rs[mt][1] += e2 + e3;
            }
        }
    }

    // Reduce row partials over the 4 threads per row group, write NPART slots
#pragma unroll
    for (int mt = 0; mt < 2; mt++)
#pragma unroll
        for (int h = 0; h < 2; h++) {
            float v = rs[mt][h];
            v += __shfl_xor_sync(0xffffffffu, v, 1);
            v += __shfl_xor_sync(0xffffffffu, v, 2);
            if (tig == 0) {
                int grow = rowBase + warpR + mt * 16 + h * 8 + g;
                g_den[(size_t)grow * NPART + sp * 2 + (wid & 1)] = v;
            }
        }
}

// ---------------------------------------------------------------------------
// 4) Per-(group, row-chunk) vector sums of zn[:B] — coalesced
// ---------------------------------------------------------------------------
__global__ void group_kernel(const long long* __restrict__ sf) {
    int blk = blockIdx.x;       // 0..63, rows [blk*64, blk*64+64)
    int t   = threadIdx.x;      // 0..255 (column)
    int base = blk * 64;
    __shared__ int sg[64];
    if (t < 64) sg[t] = (int)sf[base + t];
    __syncthreads();
    float a0 = 0.f, a1 = 0.f, a2 = 0.f, a3 = 0.f;
    for (int r = 0; r < 64; r++) {
        float v = g_zn[(size_t)(base + r) * DIMS + t];
        int gg = sg[r];
        a0 += (gg == 0) ? v : 0.f;
        a1 += (gg == 1) ? v : 0.f;
        a2 += (gg == 2) ? v : 0.f;
        a3 += (gg == 3) ? v : 0.f;
    }
    g_vpart[(0 * GCHUNK + blk) * DIMS + t] = a0;
    g_vpart[(1 * GCHUNK + blk) * DIMS + t] = a1;
    g_vpart[(2 * GCHUNK + blk) * DIMS + t] = a2;
    g_vpart[(3 * GCHUNK + blk) * DIMS + t] = a3;
}

// ---------------------------------------------------------------------------
// 5) Final deterministic reductions + scalar assembly
// ---------------------------------------------------------------------------
__global__ void final_kernel(const long long* __restrict__ sf, float* __restrict__ out) {
    int t = threadIdx.x;   // 256 threads
    __shared__ float red[256];
    __shared__ int   redi[256];
    __shared__ float gsum[NGROUP];
    __shared__ int   counts[NGROUP];

    int carr[NGROUP] = {0, 0, 0, 0};
    for (int r = t; r < BHALF; r += 256) {
        int gg = (int)sf[r];
        carr[0] += (gg == 0); carr[1] += (gg == 1);
        carr[2] += (gg == 2); carr[3] += (gg == 3);
    }
    for (int gg = 0; gg < NGROUP; gg++) {
        redi[t] = carr[gg];
        __syncthreads();
        for (int s = 128; s > 0; s >>= 1) {
            if (t < s) redi[t] += redi[t + s];
            __syncthreads();
        }
        if (t == 0) counts[gg] = redi[0];
        __syncthreads();
    }

    // group_sums[g] = || sum_{i in g} zn_i ||^2
    for (int gg = 0; gg < NGROUP; gg++) {
        float v = 0.f;
        for (int ch = 0; ch < GCHUNK; ch++) v += g_vpart[(gg * GCHUNK + ch) * DIMS + t];
        red[t] = v * v;
        __syncthreads();
        for (int s = 128; s > 0; s >>= 1) {
            if (t < s) red[t] += red[t + s];
            __syncthreads();
        }
        if (t == 0) gsum[gg] = red[0];
        __syncthreads();
    }

    // sum over rows of log(den_i)
    float l = 0.f;
    for (int r = t; r < NTOT; r += 256) {
        float d = 0.f;
#pragma unroll
        for (int s2 = 0; s2 < NPART; s2++) d += g_den[(size_t)r * NPART + s2];
        l += logf(d);
    }
    red[t] = l;
    __syncthreads();
    for (int s = 128; s > 0; s >>= 1) {
        if (t < s) red[t] += red[t + s];
        __syncthreads();
    }
    float sumlog = red[0];
    __syncthreads();

    float p = 0.f;
    for (int k = t; k < BHALF; k += 256) p += g_pos[k];
    red[t] = p;
    __syncthreads();
    for (int s = 128; s > 0; s >>= 1) {
        if (t < s) red[t] += red[t + s];
        __syncthreads();
    }

    if (t == 0) {
        float possum = red[0];
        float contrastive = (sumlog - 4.0f * possum) / (float)NTOT;  // T = 0.5
        float fair_acc = 0.f, nuniq = 0.f;
        for (int gg = 0; gg < NGROUP; gg++) {
            float c = (float)counts[gg];
            if (c > 0.f) nuniq += 1.f;
            if (c > 1.f) fair_acc += gsum[gg] / (c * (c - 1.f));
        }
        float fairness = 0.1f * (fair_acc / fmaxf(nuniq, 1.f));
        out[0] = contrastive + fairness;
    }
}

// ---------------------------------------------------------------------------
extern "C" void kernel_launch(void* const* d_in, const int* in_sizes, int n_in,
                              void* d_out, int out_size) {
    const float*     zi  = (const float*)d_in[0];
    const float*     zj  = (const float*)d_in[1];
    const long long* sf  = (const long long*)d_in[2];
    float*           out = (float*)d_out;

    cudaFuncSetAttribute(den_mma_kernel, cudaFuncAttributeMaxDynamicSharedMemorySize, SM_TOTAL);

    norm_kernel<<<NTOT, 128>>>(zi, zj);
    pos_kernel<<<BHALF, 128>>>();
    den_mma_kernel<<<dim3(64, 8), 256, SM_TOTAL>>>();
    group_kernel<<<GCHUNK, 256>>>(sf);
    final_kernel<<<1, 256>>>(sf, out);
}

// round 4
// speedup vs baseline: 6.2068x; 1.1609x over previous
#include <cuda_runtime.h>

// Problem constants (fixed by setup_inputs)
#define BHALF  4096
#define NTOT   8192
#define DIMS   256
#define NPART  16
#define NGROUP 4

// fp8 quantization scale: zn * 8 -> e4m3.  S_fp8 = 64*S.
// exp(2S) = exp2(S_fp8 * (2/ln2)/64)
#define QSCALE   8.0f
#define EXP2K    0.04508422002778011f

// ---------------------------------------------------------------------------
// Scratch (device globals; no allocations allowed)
// ---------------------------------------------------------------------------
__device__ float g_zn[(size_t)NTOT * DIMS];                          // normalized fp32 (8 MB)
__device__ __align__(1024) unsigned char g_zq[(size_t)NTOT * DIMS];  // e4m3*8, swizzled per 128-row tile (2 MB)
__device__ float g_den[(size_t)NTOT * NPART];
__device__ float g_pos[BHALF];
__device__ float g_vpart[NGROUP * 128 * DIMS];
__device__ float g_logpart[64];

// ---------------------------------------------------------------------------
// PTX helpers (family-portable: cp.async, ldmatrix, mma.sync fp8)
// ---------------------------------------------------------------------------
__device__ __forceinline__ unsigned smem_u32(const void* p) {
    unsigned a;
    asm("{ .reg .u64 t; cvta.to.shared.u64 t, %1; cvt.u32.u64 %0, t; }" : "=r"(a) : "l"(p));
    return a;
}
__device__ __forceinline__ void cp16(unsigned dst, const void* src) {
    asm volatile("cp.async.cg.shared.global [%0], [%1], 16;" :: "r"(dst), "l"(src) : "memory");
}
#define CP_COMMIT() asm volatile("cp.async.commit_group;" ::: "memory")
#define CP_WAIT(n)  asm volatile("cp.async.wait_group %0;" :: "n"(n) : "memory")

#define LDSM4(r0, r1, r2, r3, a)                                              \
    asm volatile("ldmatrix.sync.aligned.m8n8.x4.shared.b16 {%0,%1,%2,%3}, [%4];" \
                 : "=r"(r0), "=r"(r1), "=r"(r2), "=r"(r3) : "r"(a))

#define MMAFP8(d, a, b0, b1)                                                  \
    asm volatile("mma.sync.aligned.m16n8k32.row.col.f32.e4m3.e4m3.f32 "       \
                 "{%0,%1,%2,%3}, {%4,%5,%6,%7}, {%8,%9}, {%0,%1,%2,%3};"      \
                 : "+f"((d)[0]), "+f"((d)[1]), "+f"((d)[2]), "+f"((d)[3])     \
                 : "r"((a)[0]), "r"((a)[1]), "r"((a)[2]), "r"((a)[3]),        \
                   "r"(b0), "r"(b1))

// exp2(s * EXP2K * log-scale) via magic-round + deg-5 poly; s in [-64,64]
__device__ __forceinline__ float fexp2q(float s) {
    float x  = s * EXP2K;
    float fx = x + 12582912.0f;
    int   ix = __float_as_int(fx);
    float fl = fx - 12582912.0f;
    float f  = x - fl;
    float p  = 1.3333558146428443e-3f;
    p = fmaf(p, f, 9.6181291076284772e-3f);
    p = fmaf(p, f, 5.5504108664798463e-2f);
    p = fmaf(p, f, 2.4022650695910072e-1f);
    p = fmaf(p, f, 6.9314718055994531e-1f);
    p = fmaf(p, f, 1.0f);
    return __int_as_float(__float_as_int(p) + (ix << 23));
}

__device__ __forceinline__ float warp_sum(float v) {
#pragma unroll
    for (int s = 16; s > 0; s >>= 1) v += __shfl_xor_sync(0xffffffffu, v, s);
    return v;
}

// ---------------------------------------------------------------------------
// 1) Normalize (warp-per-row). Writes fp32 row + fp8(x8) row into the
//    swizzled tile layout: tile = 128 rows x 256 B; row r, 16B-chunk c at
//    byte (c ^ (r&7))*16.  Tile stride 32 KB.
// ---------------------------------------------------------------------------
__global__ void norm_kernel(const float* __restrict__ zi, const float* __restrict__ zj) {
    int wid  = threadIdx.x >> 5, lane = threadIdx.x & 31;
    int row  = blockIdx.x * 8 + wid;
    const float* src = (row < BHALF) ? (zi + (size_t)row * DIMS)
                                     : (zj + (size_t)(row - BHALF) * DIMS);
    float4 v0 = ((const float4*)src)[lane];
    float4 v1 = ((const float4*)src)[lane + 32];
    float ss = v0.x*v0.x + v0.y*v0.y + v0.z*v0.z + v0.w*v0.w
             + v1.x*v1.x + v1.y*v1.y + v1.z*v1.z + v1.w*v1.w;
    ss = warp_sum(ss);
    float inv = 1.0f / fmaxf(sqrtf(ss), 1e-8f);
    v0.x *= inv; v0.y *= inv; v0.z *= inv; v0.w *= inv;
    v1.x *= inv; v1.y *= inv; v1.z *= inv; v1.w *= inv;
    ((float4*)&g_zn[(size_t)row * DIMS])[lane]      = v0;
    ((float4*)&g_zn[(size_t)row * DIMS])[lane + 32] = v1;

    // quantize *8 -> e4m3, pack 4 bytes per store
    unsigned short p01, p23;
    unsigned w;
    int tile = row >> 7, r = row & 127;
    unsigned rowbase = (unsigned)tile * 32768u + (unsigned)r * 256u;
    unsigned rx = (unsigned)(r & 7) << 4;

    asm("cvt.rn.satfinite.e4m3x2.f32 %0, %1, %2;" : "=h"(p01) : "f"(v0.y*QSCALE), "f"(v0.x*QSCALE));
    asm("cvt.rn.satfinite.e4m3x2.f32 %0, %1, %2;" : "=h"(p23) : "f"(v0.w*QSCALE), "f"(v0.z*QSCALE));
    asm("mov.b32 %0, {%1, %2};" : "=r"(w) : "h"(p01), "h"(p23));
    {
        unsigned byteoff = (unsigned)lane * 4u;                       // cols 4*lane
        unsigned c = byteoff >> 4, o = byteoff & 15u;
        *(unsigned*)(g_zq + rowbase + (((c << 4) ^ rx)) + o) = w;
    }
    asm("cvt.rn.satfinite.e4m3x2.f32 %0, %1, %2;" : "=h"(p01) : "f"(v1.y*QSCALE), "f"(v1.x*QSCALE));
    asm("cvt.rn.satfinite.e4m3x2.f32 %0, %1, %2;" : "=h"(p23) : "f"(v1.w*QSCALE), "f"(v1.z*QSCALE));
    asm("mov.b32 %0, {%1, %2};" : "=r"(w) : "h"(p01), "h"(p23));
    {
        unsigned byteoff = 128u + (unsigned)lane * 4u;                // cols 128 + 4*lane
        unsigned c = byteoff >> 4, o = byteoff & 15u;
        *(unsigned*)(g_zq + rowbase + (((c << 4) ^ rx)) + o) = w;
    }
}

// ---------------------------------------------------------------------------
// 2) pos_k = zn[k] . zn[k+B]  (warp-per-row, fp32)
// ---------------------------------------------------------------------------
__global__ void pos_kernel() {
    int wid = threadIdx.x >> 5, lane = threadIdx.x & 31;
    int k = blockIdx.x * 8 + wid;
    const float4* a = (const float4*)&g_zn[(size_t)k * DIMS];
    const float4* b = (const float4*)&g_zn[(size_t)(k + BHALF) * DIMS];
    float4 a0 = a[lane], a1 = a[lane + 32];
    float4 b0 = b[lane], b1 = b[lane + 32];
    float d = a0.x*b0.x + a0.y*b0.y + a0.z*b0.z + a0.w*b0.w
            + a1.x*b1.x + a1.y*b1.y + a1.z*b1.z + a1.w*b1.w;
    d = warp_sum(d);
    if (lane == 0) g_pos[k] = d;
}

// ---------------------------------------------------------------------------
// 3) den pass, fp8 MMA. Grid (64 row tiles, 8 col splits); each CTA walks
//    8 B tiles (double buffered). 8 warps, warp tile 32 rows x 64 cols.
//    Tiles are 32 KB; A + 2B = 96 KB -> 2 CTAs/SM.
// ---------------------------------------------------------------------------
#define TILEB 32768
#define SMB0  32768
#define SMB1  65536
#define SM_TOTAL 98304

__global__ __launch_bounds__(256, 2) void den_mma_kernel() {
    extern __shared__ __align__(1024) unsigned char smem[];
    const unsigned sb = smem_u32(smem);
    const int tid = threadIdx.x, wid = tid >> 5, lane = tid & 31;
    const int g = lane >> 2, tig = lane & 3;
    const int warpR = (wid >> 1) * 32;
    const int warpC = (wid & 1) * 64;
    const int rowBase = blockIdx.x * 128;
    const int sp = blockIdx.y;

    // Prologue copies: A, B0 (group 0); B1 (group 1). 32 KB each = 8x4KB.
    {
        const unsigned char* As = g_zq + (size_t)blockIdx.x * TILEB;
        const unsigned char* B0 = g_zq + (size_t)(sp * 8 + 0) * TILEB;
#pragma unroll
        for (int i = 0; i < 8; i++) {
            unsigned o = i * 4096 + tid * 16;
            cp16(sb + o, As + o);
            cp16(sb + SMB0 + o, B0 + o);
        }
        CP_COMMIT();
        const unsigned char* B1 = g_zq + (size_t)(sp * 8 + 1) * TILEB;
#pragma unroll
        for (int i = 0; i < 8; i++) {
            unsigned o = i * 4096 + tid * 16;
            cp16(sb + SMB1 + o, B1 + o);
        }
        CP_COMMIT();
    }

    // Per-lane ldmatrix row bases (tile-relative). rr = lane&7.
    const int t4   = lane >> 3;          // tile index within x4
    const int rr   = lane & 7;
    const unsigned hiA = (unsigned)(lane >> 4);        // chunk +hi for A (t>>1)
    const unsigned hiB = (unsigned)((lane >> 3) & 1);  // chunk +hi for B (t&1)
    unsigned aBase[2], bBase[4];
#pragma unroll
    for (int mt = 0; mt < 2; mt++) {
        int arow = warpR + mt * 16 + ((t4 & 1) << 3) + rr;
        aBase[mt] = (unsigned)arow * 256u;
    }
#pragma unroll
    for (int q = 0; q < 4; q++) {
        int nrow = warpC + (q * 2 + (t4 >> 1)) * 8 + rr;
        bBase[q] = (unsigned)nrow * 256u;
    }

    float rs[2][2] = {{0.f, 0.f}, {0.f, 0.f}};

    for (int ct = 0; ct < 8; ct++) {
        CP_WAIT(1);
        __syncthreads();
        const unsigned sB = sb + ((ct & 1) ? SMB1 : SMB0);

        float acc[2][8][4];
#pragma unroll
        for (int mt = 0; mt < 2; mt++)
#pragma unroll
            for (int nt = 0; nt < 8; nt++)
#pragma unroll
                for (int qq = 0; qq < 4; qq++) acc[mt][nt][qq] = 0.f;

#pragma unroll
        for (int ks = 0; ks < 8; ks++) {
            unsigned ca = ((2u * ks + hiA) ^ (unsigned)rr) << 4;
            unsigned cb = ((2u * ks + hiB) ^ (unsigned)rr) << 4;
            unsigned a[2][4];
            LDSM4(a[0][0], a[0][1], a[0][2], a[0][3], sb + aBase[0] + ca);
            LDSM4(a[1][0], a[1][1], a[1][2], a[1][3], sb + aBase[1] + ca);
            unsigned b[4][4];
#pragma unroll
            for (int q = 0; q < 4; q++)
                LDSM4(b[q][0], b[q][1], b[q][2], b[q][3], sB + bBase[q] + cb);
#pragma unroll
            for (int mt = 0; mt < 2; mt++)
#pragma unroll
                for (int nt = 0; nt < 8; nt++)
                    MMAFP8(acc[mt][nt], a[mt], b[nt >> 1][(nt & 1) * 2], b[nt >> 1][(nt & 1) * 2 + 1]);
        }

        __syncthreads();                 // all warps done reading B[ct&1]
        if (ct + 2 < 8) {
            const unsigned char* Bn = g_zq + (size_t)(sp * 8 + ct + 2) * TILEB;
            unsigned sBn = sb + ((ct & 1) ? SMB1 : SMB0);
#pragma unroll
            for (int i = 0; i < 8; i++) {
                unsigned o = i * 4096 + tid * 16;
                cp16(sBn + o, Bn + o);
            }
        }
        CP_COMMIT();

        // Epilogue: exp + row-sum accumulate (overlaps prefetch)
        const bool hasDiag = ((int)blockIdx.x == sp * 8 + ct);
#pragma unroll
        for (int mt = 0; mt < 2; mt++) {
#pragma unroll
            for (int nt = 0; nt < 8; nt++) {
                float e0 = fexp2q(acc[mt][nt][0]);
                float e1 = fexp2q(acc[mt][nt][1]);
                float e2 = fexp2q(acc[mt][nt][2]);
                float e3 = fexp2q(acc[mt][nt][3]);
                if (hasDiag) {
                    int r0 = warpR + mt * 16 + g;
                    int cc = warpC + nt * 8 + tig * 2;
                    if (r0 == cc)         e0 = 0.f;
                    if (r0 == cc + 1)     e1 = 0.f;
                    if (r0 + 8 == cc)     e2 = 0.f;
                    if (r0 + 8 == cc + 1) e3 = 0.f;
                }
                rs[mt][0] += e0 + e1;
                rs[mt][1] += e2 + e3;
            }
        }
    }

    // Reduce over the 4 threads per row, write partials
#pragma unroll
    for (int mt = 0; mt < 2; mt++)
#pragma unroll
        for (int h = 0; h < 2; h++) {
            float v = rs[mt][h];
            v += __shfl_xor_sync(0xffffffffu, v, 1);
            v += __shfl_xor_sync(0xffffffffu, v, 2);
            if (tig == 0) {
                int grow = rowBase + warpR + mt * 16 + h * 8 + g;
                g_den[(size_t)grow * NPART + sp * 2 + (wid & 1)] = v;
            }
        }
}

// ---------------------------------------------------------------------------
// 4) Per-(group, row-chunk) vector sums of zn[:B]  (128 blocks x 32 rows)
// ---------------------------------------------------------------------------
__global__ void group_kernel(const long long* __restrict__ sf) {
    int blk = blockIdx.x;       // rows [blk*32, blk*32+32)
    int t   = threadIdx.x;      // column 0..255
    int base = blk * 32;
    __shared__ int sg[32];
    if (t < 32) sg[t] = (int)sf[base + t];
    __syncthreads();
    float a0 = 0.f, a1 = 0.f, a2 = 0.f, a3 = 0.f;
#pragma unroll 4
    for (int r = 0; r < 32; r++) {
        float v = g_zn[(size_t)(base + r) * DIMS + t];
        int gg = sg[r];
        a0 += (gg == 0) ? v : 0.f;
        a1 += (gg == 1) ? v : 0.f;
        a2 += (gg == 2) ? v : 0.f;
        a3 += (gg == 3) ? v : 0.f;
    }
    g_vpart[(0 * 128 + blk) * DIMS + t] = a0;
    g_vpart[(1 * 128 + blk) * DIMS + t] = a1;
    g_vpart[(2 * 128 + blk) * DIMS + t] = a2;
    g_vpart[(3 * 128 + blk) * DIMS + t] = a3;
}

// ---------------------------------------------------------------------------
// 5) Parallel log(den) partial sums: 64 blocks x 128 rows
// ---------------------------------------------------------------------------
__global__ void logden_kernel() {
    int row = blockIdx.x * 128 + threadIdx.x;
    float d = 0.f;
#pragma unroll
    for (int s = 0; s < NPART; s++) d += g_den[(size_t)row * NPART + s];
    float l = logf(d);
    __shared__ float red[128];
    red[threadIdx.x] = l;
    __syncthreads();
    for (int s = 64; s > 0; s >>= 1) {
        if (threadIdx.x < s) red[threadIdx.x] += red[threadIdx.x + s];
        __syncthreads();
    }
    if (threadIdx.x == 0) g_logpart[blockIdx.x] = red[0];
}

// ---------------------------------------------------------------------------
// 6) Final deterministic assembly
// ---------------------------------------------------------------------------
__global__ void final_kernel(const long long* __restrict__ sf, float* __restrict__ out) {
    int t = threadIdx.x;   // 256 threads
    __shared__ float red[256];
    __shared__ int   redi[256];
    __shared__ float gsum[NGROUP];
    __shared__ int   counts[NGROUP];

    int carr[NGROUP] = {0, 0, 0, 0};
    for (int r = t; r < BHALF; r += 256) {
        int gg = (int)sf[r];
        carr[0] += (gg == 0); carr[1] += (gg == 1);
        carr[2] += (gg == 2); carr[3] += (gg == 3);
    }
    for (int gg = 0; gg < NGROUP; gg++) {
        redi[t] = carr[gg];
        __syncthreads();
        for (int s = 128; s > 0; s >>= 1) {
            if (t < s) redi[t] += redi[t + s];
            __syncthreads();
        }
        if (t == 0) counts[gg] = redi[0];
        __syncthreads();
    }

    // group_sums[g] = || sum_{i in g} zn_i ||^2
    for (int gg = 0; gg < NGROUP; gg++) {
        float v = 0.f;
        for (int ch = 0; ch < 128; ch++) v += g_vpart[(gg * 128 + ch) * DIMS + t];
        red[t] = v * v;
        __syncthreads();
        for (int s = 128; s > 0; s >>= 1) {
            if (t < s) red[t] += red[t + s];
            __syncthreads();
        }
        if (t == 0) gsum[gg] = red[0];
        __syncthreads();
    }

    // sum(log den) from 64 partials
    red[t] = (t < 64) ? g_logpart[t] : 0.f;
    __syncthreads();
    for (int s = 128; s > 0; s >>= 1) {
        if (t < s) red[t] += red[t + s];
        __syncthreads();
    }
    float sumlog = red[0];
    __syncthreads();

    float p = 0.f;
    for (int k = t; k < BHALF; k += 256) p += g_pos[k];
    red[t] = p;
    __syncthreads();
    for (int s = 128; s > 0; s >>= 1) {
        if (t < s) red[t] += red[t + s];
        __syncthreads();
    }

    if (t == 0) {
        float possum = red[0];
        float contrastive = (sumlog - 4.0f * possum) / (float)NTOT;  // T = 0.5
        float fair_acc = 0.f, nuniq = 0.f;
        for (int gg = 0; gg < NGROUP; gg++) {
            float c = (float)counts[gg];
            if (c > 0.f) nuniq += 1.f;
            if (c > 1.f) fair_acc += gsum[gg] / (c * (c - 1.f));
        }
        float fairness = 0.1f * (fair_acc / fmaxf(nuniq, 1.f));
        out[0] = contrastive + fairness;
    }
}

// ---------------------------------------------------------------------------
extern "C" void kernel_launch(void* const* d_in, const int* in_sizes, int n_in,
                              void* d_out, int out_size) {
    const float*     zi  = (const float*)d_in[0];
    const float*     zj  = (const float*)d_in[1];
    const long long* sf  = (const long long*)d_in[2];
    float*           out = (float*)d_out;

    cudaFuncSetAttribute(den_mma_kernel, cudaFuncAttributeMaxDynamicSharedMemorySize, SM_TOTAL);

    norm_kernel<<<NTOT / 8, 256>>>(zi, zj);
    den_mma_kernel<<<dim3(64, 8), 256, SM_TOTAL>>>();
    pos_kernel<<<BHALF / 8, 256>>>();
    group_kernel<<<128, 256>>>(sf);
    logden_kernel<<<64, 128>>>();
    final_kernel<<<1, 256>>>(sf, out);
}

// round 5
// speedup vs baseline: 7.8684x; 1.2677x over previous
#include <cuda_runtime.h>

// Problem constants (fixed by setup_inputs)
#define BHALF  4096
#define NTOT   8192
#define DIMS   256
#define NPART  384        // per-row den partial slots: [0,128) row-role 2*ct+half,
                          // [128,384) col-role 128+4*rt+warpRidx
#define NGROUP 4
#define GBLK   256        // group_kernel blocks (16 rows each)

// fp8 quantization scale: zn * 8 -> e4m3.  S_fp8 = 64*S.
// exp(2S) = exp2(S_fp8 * (2/ln2)/64)
#define QSCALE   8.0f
#define EXP2K    0.04508422002778011f

// ---------------------------------------------------------------------------
// Scratch (device globals; no allocations allowed)
// ---------------------------------------------------------------------------
__device__ float g_zn[(size_t)NTOT * DIMS];                          // normalized fp32 (8 MB)
__device__ __align__(1024) unsigned char g_zq[(size_t)NTOT * DIMS];  // e4m3*8, swizzled per 128-row tile (2 MB)
__device__ float g_den[(size_t)NTOT * NPART];                        // 12.6 MB
__device__ float g_pos[BHALF];
__device__ float g_vpart[NGROUP * GBLK * DIMS];
__device__ float g_logpart[64];

// ---------------------------------------------------------------------------
// PTX helpers (family-portable: cp.async, ldmatrix, mma.sync fp8)
// ---------------------------------------------------------------------------
__device__ __forceinline__ unsigned smem_u32(const void* p) {
    unsigned a;
    asm("{ .reg .u64 t; cvta.to.shared.u64 t, %1; cvt.u32.u64 %0, t; }" : "=r"(a) : "l"(p));
    return a;
}
__device__ __forceinline__ void cp16(unsigned dst, const void* src) {
    asm volatile("cp.async.cg.shared.global [%0], [%1], 16;" :: "r"(dst), "l"(src) : "memory");
}
#define CP_COMMIT() asm volatile("cp.async.commit_group;" ::: "memory")
#define CP_WAIT(n)  asm volatile("cp.async.wait_group %0;" :: "n"(n) : "memory")

#define LDSM4(r0, r1, r2, r3, a)                                              \
    asm volatile("ldmatrix.sync.aligned.m8n8.x4.shared.b16 {%0,%1,%2,%3}, [%4];" \
                 : "=r"(r0), "=r"(r1), "=r"(r2), "=r"(r3) : "r"(a))

#define MMAFP8(d, a, b0, b1)                                                  \
    asm volatile("mma.sync.aligned.m16n8k32.row.col.f32.e4m3.e4m3.f32 "       \
                 "{%0,%1,%2,%3}, {%4,%5,%6,%7}, {%8,%9}, {%0,%1,%2,%3};"      \
                 : "+f"((d)[0]), "+f"((d)[1]), "+f"((d)[2]), "+f"((d)[3])     \
                 : "r"((a)[0]), "r"((a)[1]), "r"((a)[2]), "r"((a)[3]),        \
                   "r"(b0), "r"(b1))

// exp2(s * EXP2K) via magic-round + deg-5 poly; s in [-64,64]
__device__ __forceinline__ float fexp2q(float s) {
    float x  = s * EXP2K;
    float fx = x + 12582912.0f;
    int   ix = __float_as_int(fx);
    float fl = fx - 12582912.0f;
    float f  = x - fl;
    float p  = 1.3333558146428443e-3f;
    p = fmaf(p, f, 9.6181291076284772e-3f);
    p = fmaf(p, f, 5.5504108664798463e-2f);
    p = fmaf(p, f, 2.4022650695910072e-1f);
    p = fmaf(p, f, 6.9314718055994531e-1f);
    p = fmaf(p, f, 1.0f);
    return __int_as_float(__float_as_int(p) + (ix << 23));
}

__device__ __forceinline__ float warp_sum(float v) {
#pragma unroll
    for (int s = 16; s > 0; s >>= 1) v += __shfl_xor_sync(0xffffffffu, v, s);
    return v;
}

// ---------------------------------------------------------------------------
// 1) Normalize (warp-per-row). fp32 row + fp8(x8) row into swizzled tile
//    layout: tile = 128 rows x 256 B; row r, 16B-chunk c at byte (c^(r&7))*16.
// ---------------------------------------------------------------------------
__global__ void norm_kernel(const float* __restrict__ zi, const float* __restrict__ zj) {
    int wid  = threadIdx.x >> 5, lane = threadIdx.x & 31;
    int row  = blockIdx.x * 8 + wid;
    const float* src = (row < BHALF) ? (zi + (size_t)row * DIMS)
                                     : (zj + (size_t)(row - BHALF) * DIMS);
    float4 v0 = ((const float4*)src)[lane];
    float4 v1 = ((const float4*)src)[lane + 32];
    float ss = v0.x*v0.x + v0.y*v0.y + v0.z*v0.z + v0.w*v0.w
             + v1.x*v1.x + v1.y*v1.y + v1.z*v1.z + v1.w*v1.w;
    ss = warp_sum(ss);
    float inv = 1.0f / fmaxf(sqrtf(ss), 1e-8f);
    v0.x *= inv; v0.y *= inv; v0.z *= inv; v0.w *= inv;
    v1.x *= inv; v1.y *= inv; v1.z *= inv; v1.w *= inv;
    ((float4*)&g_zn[(size_t)row * DIMS])[lane]      = v0;
    ((float4*)&g_zn[(size_t)row * DIMS])[lane + 32] = v1;

    unsigned short p01, p23;
    unsigned w;
    int tile = row >> 7, r = row & 127;
    unsigned rowbase = (unsigned)tile * 32768u + (unsigned)r * 256u;
    unsigned rx = (unsigned)(r & 7) << 4;

    asm("cvt.rn.satfinite.e4m3x2.f32 %0, %1, %2;" : "=h"(p01) : "f"(v0.y*QSCALE), "f"(v0.x*QSCALE));
    asm("cvt.rn.satfinite.e4m3x2.f32 %0, %1, %2;" : "=h"(p23) : "f"(v0.w*QSCALE), "f"(v0.z*QSCALE));
    asm("mov.b32 %0, {%1, %2};" : "=r"(w) : "h"(p01), "h"(p23));
    {
        unsigned byteoff = (unsigned)lane * 4u;
        unsigned c = byteoff >> 4, o = byteoff & 15u;
        *(unsigned*)(g_zq + rowbase + (((c << 4) ^ rx)) + o) = w;
    }
    asm("cvt.rn.satfinite.e4m3x2.f32 %0, %1, %2;" : "=h"(p01) : "f"(v1.y*QSCALE), "f"(v1.x*QSCALE));
    asm("cvt.rn.satfinite.e4m3x2.f32 %0, %1, %2;" : "=h"(p23) : "f"(v1.w*QSCALE), "f"(v1.z*QSCALE));
    asm("mov.b32 %0, {%1, %2};" : "=r"(w) : "h"(p01), "h"(p23));
    {
        unsigned byteoff = 128u + (unsigned)lane * 4u;
        unsigned c = byteoff >> 4, o = byteoff & 15u;
        *(unsigned*)(g_zq + rowbase + (((c << 4) ^ rx)) + o) = w;
    }
}

// ---------------------------------------------------------------------------
// 2) pos_k = zn[k] . zn[k+B]  (warp-per-row, fp32)
// ---------------------------------------------------------------------------
__global__ void pos_kernel() {
    int wid = threadIdx.x >> 5, lane = threadIdx.x & 31;
    int k = blockIdx.x * 8 + wid;
    const float4* a = (const float4*)&g_zn[(size_t)k * DIMS];
    const float4* b = (const float4*)&g_zn[(size_t)(k + BHALF) * DIMS];
    float4 a0 = a[lane], a1 = a[lane + 32];
    float4 b0 = b[lane], b1 = b[lane + 32];
    float d = a0.x*b0.x + a0.y*b0.y + a0.z*b0.z + a0.w*b0.w
            + a1.x*b1.x + a1.y*b1.y + a1.z*b1.z + a1.w*b1.w;
    d = warp_sum(d);
    if (lane == 0) g_pos[k] = d;
}

// ---------------------------------------------------------------------------
// 3) den pass, fp8 MMA, UPPER TRIANGLE only (2080 blocks).
//    Block (rt,ct), rt<=ct: compute exp tile once; row sums -> rows of rt,
//    col sums -> rows of ct (symmetry). Diagonal blocks: row sums only,
//    zeroed diagonal. 8 warps, warp tile 32 rows x 64 cols.
// ---------------------------------------------------------------------------
#define TILEB 32768
#define NBLK  2080
#define SM_TOTAL 65536

__global__ __launch_bounds__(256, 2) void den_mma_kernel() {
    extern __shared__ __align__(1024) unsigned char smem[];
    const unsigned sb = smem_u32(smem);
    const int tid = threadIdx.x, wid = tid >> 5, lane = tid & 31;
    const int g = lane >> 2, tig = lane & 3;
    const int warpRi = wid >> 1;               // 0..3
    const int warpR  = warpRi * 32;
    const int warpC  = (wid & 1) * 64;

    // bid -> (rt, ct) upper triangle incl. diagonal
    int rem = blockIdx.x, rt = 0;
    while (rem >= 64 - rt) { rem -= 64 - rt; rt++; }
    const int ct = rt + rem;
    const bool isDiag = (rt == ct);

    // Load A tile (rt); B tile (ct) unless diagonal (reuse A)
    {
        const unsigned char* As = g_zq + (size_t)rt * TILEB;
        const unsigned char* Bs = g_zq + (size_t)ct * TILEB;
#pragma unroll
        for (int i = 0; i < 8; i++) {
            unsigned o = i * 4096 + tid * 16;
            cp16(sb + o, As + o);
            if (!isDiag) cp16(sb + TILEB + o, Bs + o);
        }
        CP_COMMIT();
    }
    const unsigned sB = isDiag ? sb : (sb + TILEB);

    // Per-lane ldmatrix row bases (tile-relative)
    const int t4 = lane >> 3;
    const int rr = lane & 7;
    const unsigned hiA = (unsigned)(lane >> 4);
    const unsigned hiB = (unsigned)((lane >> 3) & 1);
    unsigned aBase[2], bBase[4];
#pragma unroll
    for (int mt = 0; mt < 2; mt++) {
        int arow = warpR + mt * 16 + ((t4 & 1) << 3) + rr;
        aBase[mt] = (unsigned)arow * 256u;
    }
#pragma unroll
    for (int q = 0; q < 4; q++) {
        int nrow = warpC + (q * 2 + (t4 >> 1)) * 8 + rr;
        bBase[q] = (unsigned)nrow * 256u;
    }

    float acc[2][8][4];
#pragma unroll
    for (int mt = 0; mt < 2; mt++)
#pragma unroll
        for (int nt = 0; nt < 8; nt++)
#pragma unroll
            for (int qq = 0; qq < 4; qq++) acc[mt][nt][qq] = 0.f;

    CP_WAIT(0);
    __syncthreads();

#pragma unroll
    for (int ks = 0; ks < 8; ks++) {
        unsigned ca = ((2u * ks + hiA) ^ (unsigned)rr) << 4;
        unsigned cb = ((2u * ks + hiB) ^ (unsigned)rr) << 4;
        unsigned a[2][4];
        LDSM4(a[0][0], a[0][1], a[0][2], a[0][3], sb + aBase[0] + ca);
        LDSM4(a[1][0], a[1][1], a[1][2], a[1][3], sb + aBase[1] + ca);
        unsigned b[4][4];
#pragma unroll
        for (int q = 0; q < 4; q++)
            LDSM4(b[q][0], b[q][1], b[q][2], b[q][3], sB + bBase[q] + cb);
#pragma unroll
        for (int mt = 0; mt < 2; mt++)
#pragma unroll
            for (int nt = 0; nt < 8; nt++)
                MMAFP8(acc[mt][nt], a[mt], b[nt >> 1][(nt & 1) * 2], b[nt >> 1][(nt & 1) * 2 + 1]);
    }

    // Epilogue: exp + row sums (+ col sums for off-diagonal)
    float rs[2][2] = {{0.f, 0.f}, {0.f, 0.f}};
    float cs[8][2];
#pragma unroll
    for (int nt = 0; nt < 8; nt++) { cs[nt][0] = 0.f; cs[nt][1] = 0.f; }

#pragma unroll
    for (int mt = 0; mt < 2; mt++) {
#pragma unroll
        for (int nt = 0; nt < 8; nt++) {
            float e0 = fexp2q(acc[mt][nt][0]);
            float e1 = fexp2q(acc[mt][nt][1]);
            float e2 = fexp2q(acc[mt][nt][2]);
            float e3 = fexp2q(acc[mt][nt][3]);
            if (isDiag) {
                int r0 = warpR + mt * 16 + g;
                int cc = warpC + nt * 8 + tig * 2;
                if (r0 == cc)         e0 = 0.f;
                if (r0 == cc + 1)     e1 = 0.f;
                if (r0 + 8 == cc)     e2 = 0.f;
                if (r0 + 8 == cc + 1) e3 = 0.f;
            } else {
                cs[nt][0] += e0 + e2;
                cs[nt][1] += e1 + e3;
            }
            rs[mt][0] += e0 + e1;
            rs[mt][1] += e2 + e3;
        }
    }

    // Row partial writes: slot = 2*ct + (wid&1)
    {
        const int slot = 2 * ct + (wid & 1);
#pragma unroll
        for (int mt = 0; mt < 2; mt++)
#pragma unroll
            for (int h = 0; h < 2; h++) {
                float v = rs[mt][h];
                v += __shfl_xor_sync(0xffffffffu, v, 1);
                v += __shfl_xor_sync(0xffffffffu, v, 2);
                if (tig == 0) {
                    int grow = rt * 128 + warpR + mt * 16 + h * 8 + g;
                    g_den[(size_t)grow * NPART + slot] = v;
                }
            }
    }

    // Col partial writes (off-diagonal): slot = 128 + 4*rt + warpRi
    if (!isDiag) {
        const int slot = 128 + 4 * rt + warpRi;
#pragma unroll
        for (int nt = 0; nt < 8; nt++) {
#pragma unroll
            for (int j = 0; j < 2; j++) {
                float v = cs[nt][j];
                v += __shfl_xor_sync(0xffffffffu, v, 4);
                v += __shfl_xor_sync(0xffffffffu, v, 8);
                v += __shfl_xor_sync(0xffffffffu, v, 16);
                if (lane < 4) {
                    int gcol = ct * 128 + warpC + nt * 8 + lane * 2 + j;
                    g_den[(size_t)gcol * NPART + slot] = v;
                }
            }
        }
    }
}

// ---------------------------------------------------------------------------
// 4) Per-(group, row-chunk) vector sums of zn[:B]  (256 blocks x 16 rows)
// ---------------------------------------------------------------------------
__global__ void group_kernel(const long long* __restrict__ sf) {
    int blk = blockIdx.x;       // rows [blk*16, blk*16+16)
    int t   = threadIdx.x;      // column 0..255
    int base = blk * 16;
    __shared__ int sg[16];
    if (t < 16) sg[t] = (int)sf[base + t];
    __syncthreads();
    float a0 = 0.f, a1 = 0.f, a2 = 0.f, a3 = 0.f;
#pragma unroll
    for (int r = 0; r < 16; r++) {
        float v = g_zn[(size_t)(base + r) * DIMS + t];
        int gg = sg[r];
        a0 += (gg == 0) ? v : 0.f;
        a1 += (gg == 1) ? v : 0.f;
        a2 += (gg == 2) ? v : 0.f;
        a3 += (gg == 3) ? v : 0.f;
    }
    g_vpart[(0 * GBLK + blk) * DIMS + t] = a0;
    g_vpart[(1 * GBLK + blk) * DIMS + t] = a1;
    g_vpart[(2 * GBLK + blk) * DIMS + t] = a2;
    g_vpart[(3 * GBLK + blk) * DIMS + t] = a3;
}

// ---------------------------------------------------------------------------
// 5) log(den): sum the statically-known written slot set, fixed order
// ---------------------------------------------------------------------------
__global__ void logden_kernel() {
    int row = blockIdx.x * 128 + threadIdx.x;
    int rt  = row >> 7;
    const float* dr = &g_den[(size_t)row * NPART];
    float d = 0.f;
    for (int o = rt; o < 64; o++) d += dr[2 * o] + dr[2 * o + 1];
    for (int s = 128; s < 128 + 4 * rt; s++) d += dr[s];
    float l = logf(d);
    __shared__ float red[128];
    red[threadIdx.x] = l;
    __syncthreads();
    for (int s = 64; s > 0; s >>= 1) {
        if (threadIdx.x < s) red[threadIdx.x] += red[threadIdx.x + s];
        __syncthreads();
    }
    if (threadIdx.x == 0) g_logpart[blockIdx.x] = red[0];
}

// ---------------------------------------------------------------------------
// 6) Final deterministic assembly
// ---------------------------------------------------------------------------
__global__ void final_kernel(const long long* __restrict__ sf, float* __restrict__ out) {
    int t = threadIdx.x;   // 256 threads
    __shared__ float red[256];
    __shared__ int   redi[256];
    __shared__ float gsum[NGROUP];
    __shared__ int   counts[NGROUP];

    int carr[NGROUP] = {0, 0, 0, 0};
    for (int r = t; r < BHALF; r += 256) {
        int gg = (int)sf[r];
        carr[0] += (gg == 0); carr[1] += (gg == 1);
        carr[2] += (gg == 2); carr[3] += (gg == 3);
    }
    for (int gg = 0; gg < NGROUP; gg++) {
        redi[t] = carr[gg];
        __syncthreads();
        for (int s = 128; s > 0; s >>= 1) {
            if (t < s) redi[t] += redi[t + s];
            __syncthreads();
        }
        if (t == 0) counts[gg] = redi[0];
        __syncthreads();
    }

    // group_sums[g] = || sum_{i in g} zn_i ||^2
    for (int gg = 0; gg < NGROUP; gg++) {
        float v = 0.f;
        for (int ch = 0; ch < GBLK; ch++) v += g_vpart[(gg * GBLK + ch) * DIMS + t];
        red[t] = v * v;
        __syncthreads();
        for (int s = 128; s > 0; s >>= 1) {
            if (t < s) red[t] += red[t + s];
            __syncthreads();
        }
        if (t == 0) gsum[gg] = red[0];
        __syncthreads();
    }

    // sum(log den) from 64 partials
    red[t] = (t < 64) ? g_logpart[t] : 0.f;
    __syncthreads();
    for (int s = 128; s > 0; s >>= 1) {
        if (t < s) red[t] += red[t + s];
        __syncthreads();
    }
    float sumlog = red[0];
    __syncthreads();

    float p = 0.f;
    for (int k = t; k < BHALF; k += 256) p += g_pos[k];
    red[t] = p;
    __syncthreads();
    for (int s = 128; s > 0; s >>= 1) {
        if (t < s) red[t] += red[t + s];
        __syncthreads();
    }

    if (t == 0) {
        float possum = red[0];
        float contrastive = (sumlog - 4.0f * possum) / (float)NTOT;  // T = 0.5
        float fair_acc = 0.f, nuniq = 0.f;
        for (int gg = 0; gg < NGROUP; gg++) {
            float c = (float)counts[gg];
            if (c > 0.f) nuniq += 1.f;
            if (c > 1.f) fair_acc += gsum[gg] / (c * (c - 1.f));
        }
        float fairness = 0.1f * (fair_acc / fmaxf(nuniq, 1.f));
        out[0] = contrastive + fairness;
    }
}

// ---------------------------------------------------------------------------
extern "C" void kernel_launch(void* const* d_in, const int* in_sizes, int n_in,
                              void* d_out, int out_size) {
    const float*     zi  = (const float*)d_in[0];
    const float*     zj  = (const float*)d_in[1];
    const long long* sf  = (const long long*)d_in[2];
    float*           out = (float*)d_out;

    cudaFuncSetAttribute(den_mma_kernel, cudaFuncAttributeMaxDynamicSharedMemorySize, SM_TOTAL);

    norm_kernel<<<NTOT / 8, 256>>>(zi, zj);
    den_mma_kernel<<<NBLK, 256, SM_TOTAL>>>();
    pos_kernel<<<BHALF / 8, 256>>>();
    group_kernel<<<GBLK, 256>>>(sf);
    logden_kernel<<<64, 128>>>();
    final_kernel<<<1, 256>>>(sf, out);
}